// round 1
// baseline (speedup 1.0000x reference)
#include <cuda_runtime.h>

// GRU_12962211299468 : B=65536, T=9, I=57, H=2, O=1, fp32
// One thread per batch element. Per-timestep cooperative smem staging of the
// x tile (coalesced), float4 dot products against W_ih staged in smem,
// recurrence + FC fused, single pass over x (134 MB).

#define B_TOTAL 65536
#define T_STEPS 9
#define I_DIM   57
#define ROW     60          // padded smem row stride (16B-aligned float4 rows)
#define NB      64          // batch elements (=threads) per block
#define XSTRIDE (T_STEPS * I_DIM)   // 513 floats per batch element

__device__ __forceinline__ float sigf(float v) {
    return 1.0f / (1.0f + __expf(-v));
}
__device__ __forceinline__ float tanh_ex(float v) {
    // tanh(x) = 1 - 2/(exp(2x)+1); __expf rel err ~2^-21, plenty for 1e-3 gate
    return 1.0f - 2.0f / (__expf(2.0f * v) + 1.0f);
}

__global__ __launch_bounds__(NB) void gru_kernel(
    const float* __restrict__ x,
    const float* __restrict__ Wih,   // [6,57]
    const float* __restrict__ Whh,   // [6,2]
    const float* __restrict__ bih,   // [6]
    const float* __restrict__ bhh,   // [6]
    const float* __restrict__ fcw,   // [2]
    const float* __restrict__ fcb,   // [1]
    float* __restrict__ out)         // [B]
{
    __shared__ float sx[NB * ROW];   // x tile for one timestep, padded rows
    __shared__ float sw[6 * ROW];    // W_ih, padded rows

    const int tid  = threadIdx.x;
    const int lane = tid & 31;
    const int wid  = tid >> 5;       // 0 or 1
    const int b0   = blockIdx.x * NB;

    // ---- stage W_ih into smem (padded) ----
    for (int f = tid; f < 6 * ROW; f += NB) sw[f] = 0.0f;
    __syncthreads();
    for (int f = tid; f < 6 * I_DIM; f += NB) {
        int g = f / I_DIM;
        int i = f - g * I_DIM;
        sw[g * ROW + i] = Wih[f];
    }

    // ---- per-thread small constants (broadcast loads, L1-resident) ----
    float whh0[6], whh1[6], bi[6], bh[6];
#pragma unroll
    for (int g = 0; g < 6; ++g) {
        whh0[g] = Whh[2 * g + 0];
        whh1[g] = Whh[2 * g + 1];
        bi[g]   = bih[g];
        bh[g]   = bhh[g];
    }
    const float fw0 = fcw[0], fw1 = fcw[1], fb = fcb[0];

    float h0 = 0.0f, h1 = 0.0f;

    // Global base of this block's x region (fully contiguous NB*513 floats)
    const float* xblk = x + (size_t)b0 * XSTRIDE;

    for (int t = 0; t < T_STEPS; ++t) {
        __syncthreads();   // previous tile fully consumed (also covers sw fill at t=0)

        // ---- cooperative coalesced load of tile [NB][57] for this t ----
        // warp w handles rows {w, w+2, w+4, ...}; lane covers i and i+32.
        {
            const float* gsrc = xblk + (size_t)wid * XSTRIDE + t * I_DIM + lane;
            float*       sdst = sx + wid * ROW + lane;
            const bool second = (lane < I_DIM - 32);   // lane < 25
#pragma unroll
            for (int r = 0; r < NB / 2; ++r) {
                float v0 = __ldg(gsrc);
                sdst[0] = v0;
                if (second) sdst[32] = __ldg(gsrc + 32);
                gsrc += 2 * XSTRIDE;
                sdst += 2 * ROW;
            }
        }
        __syncthreads();

        // ---- gx = W_ih . x_t + b_ih (6 gates) ----
        float gg[6];
#pragma unroll
        for (int g = 0; g < 6; ++g) gg[g] = bi[g];

        const float* rowp = &sx[tid * ROW];
#pragma unroll
        for (int c = 0; c < 14; ++c) {           // i = 0..55 as float4
            float4 xv = *reinterpret_cast<const float4*>(rowp + 4 * c);
#pragma unroll
            for (int g = 0; g < 6; ++g) {
                float4 wv = *reinterpret_cast<const float4*>(sw + g * ROW + 4 * c);
                gg[g] += wv.x * xv.x;
                gg[g] += wv.y * xv.y;
                gg[g] += wv.z * xv.z;
                gg[g] += wv.w * xv.w;
            }
        }
        {                                        // i = 56 tail
            float xs = rowp[56];
#pragma unroll
            for (int g = 0; g < 6; ++g) gg[g] += sw[g * ROW + 56] * xs;
        }

        // ---- recurrence ----
        float a0 = whh0[0] * h0 + whh1[0] * h1 + bh[0];
        float a1 = whh0[1] * h0 + whh1[1] * h1 + bh[1];
        float a2 = whh0[2] * h0 + whh1[2] * h1 + bh[2];
        float a3 = whh0[3] * h0 + whh1[3] * h1 + bh[3];
        float a4 = whh0[4] * h0 + whh1[4] * h1 + bh[4];
        float a5 = whh0[5] * h0 + whh1[5] * h1 + bh[5];

        float r0 = sigf(gg[0] + a0);
        float r1 = sigf(gg[1] + a1);
        float z0 = sigf(gg[2] + a2);
        float z1 = sigf(gg[3] + a3);
        float n0 = tanh_ex(gg[4] + r0 * a4);
        float n1 = tanh_ex(gg[5] + r1 * a5);

        h0 = (1.0f - z0) * n0 + z0 * h0;
        h1 = (1.0f - z1) * n1 + z1 * h1;
    }

    out[b0 + tid] = fw0 * h0 + fw1 * h1 + fb;
}

extern "C" void kernel_launch(void* const* d_in, const int* in_sizes, int n_in,
                              void* d_out, int out_size) {
    const float* x    = (const float*)d_in[0];
    const float* Wih  = (const float*)d_in[1];
    const float* Whh  = (const float*)d_in[2];
    const float* bih  = (const float*)d_in[3];
    const float* bhh  = (const float*)d_in[4];
    const float* fcw  = (const float*)d_in[5];
    const float* fcb  = (const float*)d_in[6];
    float* out = (float*)d_out;

    (void)in_sizes; (void)n_in; (void)out_size;

    gru_kernel<<<B_TOTAL / NB, NB>>>(x, Wih, Whh, bih, bhh, fcw, fcb, out);
}

// round 2
// speedup vs baseline: 1.0439x; 1.0439x over previous
#include <cuda_runtime.h>

// GRU_12962211299468 : B=65536, T=9, I=57, H=2, O=1, fp32
// Fused single-pass kernel. Each block owns 16 full batch elements:
//   phase 0: bulk-stage the block's contiguous 8208-float x region (uint4)
//   phase 1: 144 threads compute gx for one (b,t) row each  (6 x 57 dots)
//   phase 2: 16 lanes run the 9-step recurrence + FC from smem
// 4096 blocks x 160 threads -> ~20k warps of work (vs 2048 in round 1).

#define T_STEPS 9
#define I_DIM   57
#define NBATCH  16                       // batch elements per block
#define NROWS   (NBATCH * T_STEPS)       // 144 (b,t) rows per block
#define NTHR    160                      // 5 warps
#define XFLT    (NROWS * I_DIM)          // 8208 floats per block (contiguous)
#define XV4     (XFLT / 4)               // 2052 uint4
#define WROW    60                       // padded W_ih row (16B aligned)

__device__ __forceinline__ float sigf(float v) {
    return 1.0f / (1.0f + __expf(-v));
}
__device__ __forceinline__ float tanh_ex(float v) {
    return 1.0f - 2.0f / (__expf(2.0f * v) + 1.0f);
}

__global__ __launch_bounds__(NTHR) void gru_fused(
    const float* __restrict__ x,
    const float* __restrict__ Wih,   // [6,57]
    const float* __restrict__ Whh,   // [6,2]
    const float* __restrict__ bih,   // [6]
    const float* __restrict__ bhh,   // [6]
    const float* __restrict__ fcw,   // [2]
    const float* __restrict__ fcb,   // [1]
    float* __restrict__ out)         // [B]
{
    __shared__ float sx[XFLT];           // 32832 B : x tile, unpadded rows
    __shared__ float sw[6 * WROW];       //  1440 B : W_ih padded rows
    __shared__ float sgx[NROWS * 6];     //  3456 B : gate pre-activations

    const int tid = threadIdx.x;
    const int b0  = blockIdx.x * NBATCH;

    // ---- stage W_ih (single pass incl. zero padding: no WAW hazard) ----
    for (int j = tid; j < 6 * WROW; j += NTHR) {
        int g = j / WROW;
        int i = j - g * WROW;
        sw[j] = (i < I_DIM) ? Wih[g * I_DIM + i] : 0.0f;
    }

    // ---- stage x tile: fully contiguous, vectorized, coalesced ----
    {
        const uint4* gsrc = reinterpret_cast<const uint4*>(x) +
                            (size_t)blockIdx.x * XV4;
        uint4* sdst = reinterpret_cast<uint4*>(sx);
#pragma unroll
        for (int j = tid; j < XV4; j += NTHR)
            sdst[j] = __ldg(gsrc + j);
    }
    __syncthreads();

    // ---- phase 1: per-row gate projection gx = W_ih . x_row + b_ih ----
    if (tid < NROWS) {
        const float* row = &sx[tid * I_DIM];   // scalar LDS: stride 57 -> conflict-free

        float gg[6];
#pragma unroll
        for (int g = 0; g < 6; ++g) gg[g] = bih[g];

#pragma unroll
        for (int c = 0; c < 14; ++c) {
            float x0 = row[4 * c + 0];
            float x1 = row[4 * c + 1];
            float x2 = row[4 * c + 2];
            float x3 = row[4 * c + 3];
#pragma unroll
            for (int g = 0; g < 6; ++g) {
                float4 wv = *reinterpret_cast<const float4*>(&sw[g * WROW + 4 * c]);
                gg[g] += wv.x * x0;
                gg[g] += wv.y * x1;
                gg[g] += wv.z * x2;
                gg[g] += wv.w * x3;
            }
        }
        {
            float xs = row[56];
#pragma unroll
            for (int g = 0; g < 6; ++g) gg[g] += sw[g * WROW + 56] * xs;
        }

#pragma unroll
        for (int g = 0; g < 6; ++g) sgx[tid * 6 + g] = gg[g];
    }
    __syncthreads();

    // ---- phase 2: recurrence + FC for 16 batch elements ----
    if (tid < NBATCH) {
        const float w00 = Whh[0],  w01 = Whh[1];
        const float w10 = Whh[2],  w11 = Whh[3];
        const float w20 = Whh[4],  w21 = Whh[5];
        const float w30 = Whh[6],  w31 = Whh[7];
        const float w40 = Whh[8],  w41 = Whh[9];
        const float w50 = Whh[10], w51 = Whh[11];
        const float bh0 = bhh[0], bh1 = bhh[1], bh2 = bhh[2];
        const float bh3 = bhh[3], bh4 = bhh[4], bh5 = bhh[5];

        float h0 = 0.0f, h1 = 0.0f;
        const float* gp = &sgx[tid * (T_STEPS * 6)];   // stride 54 words: conflict-free

#pragma unroll
        for (int t = 0; t < T_STEPS; ++t) {
            float g0 = gp[6 * t + 0];
            float g1 = gp[6 * t + 1];
            float g2 = gp[6 * t + 2];
            float g3 = gp[6 * t + 3];
            float g4 = gp[6 * t + 4];
            float g5 = gp[6 * t + 5];

            float a0 = w00 * h0 + w01 * h1 + bh0;
            float a1 = w10 * h0 + w11 * h1 + bh1;
            float a2 = w20 * h0 + w21 * h1 + bh2;
            float a3 = w30 * h0 + w31 * h1 + bh3;
            float a4 = w40 * h0 + w41 * h1 + bh4;
            float a5 = w50 * h0 + w51 * h1 + bh5;

            float r0 = sigf(g0 + a0);
            float r1 = sigf(g1 + a1);
            float z0 = sigf(g2 + a2);
            float z1 = sigf(g3 + a3);
            float n0 = tanh_ex(g4 + r0 * a4);
            float n1 = tanh_ex(g5 + r1 * a5);

            h0 = (1.0f - z0) * n0 + z0 * h0;
            h1 = (1.0f - z1) * n1 + z1 * h1;
        }

        out[b0 + tid] = fcw[0] * h0 + fcw[1] * h1 + fcb[0];
    }
}

extern "C" void kernel_launch(void* const* d_in, const int* in_sizes, int n_in,
                              void* d_out, int out_size) {
    const float* x   = (const float*)d_in[0];
    const float* Wih = (const float*)d_in[1];
    const float* Whh = (const float*)d_in[2];
    const float* bih = (const float*)d_in[3];
    const float* bhh = (const float*)d_in[4];
    const float* fcw = (const float*)d_in[5];
    const float* fcb = (const float*)d_in[6];
    float* out = (float*)d_out;

    (void)in_sizes; (void)n_in; (void)out_size;

    gru_fused<<<65536 / NBATCH, NTHR>>>(x, Wih, Whh, bih, bhh, fcw, fcb, out);
}